// round 3
// baseline (speedup 1.0000x reference)
#include <cuda_runtime.h>

#define NG 8
#define HW 4096          // 64*64, = 2^12
#define CH 256
#define CG 4             // channels per gather block

// Scratch (device globals — no allocation allowed).
// Per (g, j): count + up to 4 (source index, coefficient) pairs.
__device__ int    g_cnt[NG * HW];
__device__ int4   g_idx4[NG * HW];
__device__ float4 g_val4[NG * HW];

__global__ void zero_cnt_kernel() {
    int t = blockIdx.x * blockDim.x + threadIdx.x;
    if (t < NG * HW) g_cnt[t] = 0;
}

// Pass 1: stream the dense matrix, extract nonzeros into fixed 4-slot CSR.
// mt layout: [g, i, j] row-major; element (g,i,j) at g*2^24 + i*2^12 + j.
__global__ void extract_kernel(const float* __restrict__ mt) {
    long long e = (long long)blockIdx.x * blockDim.x + threadIdx.x;  // float4 index
    const float4* mt4 = (const float4*)mt;
    float4 v = __ldcs(&mt4[e]);   // streaming load: read-once, don't pollute L2

    long long base = e << 2;
    int g   = (int)(base >> 24);          // HW*HW = 2^24
    int rem = (int)(base & 0xFFFFFF);
    int i   = rem >> 12;
    int j0  = rem & 0xFFF;

    float vv[4] = {v.x, v.y, v.z, v.w};
    int gb = g * HW;
    #pragma unroll
    for (int k = 0; k < 4; k++) {
        if (vv[k] != 0.0f) {
            int j = j0 + k;
            int p = atomicAdd(&g_cnt[gb + j], 1);
            if (p < 4) {
                ((int*)g_idx4)[(long long)(gb + j) * 4 + p]   = i;
                ((float*)g_val4)[(long long)(gb + j) * 4 + p] = vv[k];
            }
        }
    }
}

__device__ __forceinline__ void cswap(int& ia, float& va, int& ib, float& vb) {
    if (ia > ib) {
        int ti = ia; ia = ib; ib = ti;
        float tv = va; va = vb; vb = tv;
    }
}

// Pass 2: gather. Block = (g, 4-channel group). x rows staged in smem.
__global__ void gather_kernel(const float* __restrict__ x, float* __restrict__ out) {
    extern __shared__ float xs[];                 // CG * HW floats = 64 KB
    int g     = blockIdx.x / (CH / CG);
    int cbase = (blockIdx.x % (CH / CG)) * CG;

    const float* xg = x + ((long long)g * CH + cbase) * HW;   // CG contiguous rows
    const float4* xg4 = (const float4*)xg;
    float4* xs4 = (float4*)xs;
    for (int t = threadIdx.x; t < (CG * HW) / 4; t += blockDim.x)
        xs4[t] = xg4[t];
    __syncthreads();

    int gb = g * HW;
    for (int j = threadIdx.x; j < HW; j += blockDim.x) {
        int   cnt = g_cnt[gb + j];
        int4  id  = g_idx4[gb + j];
        float4 vl = g_val4[gb + j];

        int   i0 = id.x, i1 = id.y, i2 = id.z, i3 = id.w;
        float v0 = vl.x, v1 = vl.y, v2 = vl.z, v3 = vl.w;
        if (cnt < 4) { i3 = 0; v3 = 0.0f; }
        if (cnt < 3) { i2 = 0; v2 = 0.0f; }
        if (cnt < 2) { i1 = 0; v1 = 0.0f; }
        if (cnt < 1) { i0 = 0; v0 = 0.0f; }

        // Sort 4 pairs by source index (deterministic summation order
        // regardless of atomic append order in pass 1).
        cswap(i0, v0, i1, v1);
        cswap(i2, v2, i3, v3);
        cswap(i0, v0, i2, v2);
        cswap(i1, v1, i3, v3);
        cswap(i1, v1, i2, v2);

        #pragma unroll
        for (int c = 0; c < CG; c++) {
            const float* row = xs + c * HW;
            float s = fmaf(v3, row[i3],
                      fmaf(v2, row[i2],
                      fmaf(v1, row[i1],
                           v0 * row[i0])));
            out[((long long)(g * CH + cbase + c)) * HW + j] = s;
        }
    }
}

extern "C" void kernel_launch(void* const* d_in, const int* in_sizes, int n_in,
                              void* d_out, int out_size) {
    const float* x  = (const float*)d_in[0];   // [8, 256, 64, 64]
    const float* mt = (const float*)d_in[1];   // [8, 4096, 4096]
    float* out = (float*)d_out;

    (void)in_sizes; (void)n_in; (void)out_size;

    cudaFuncSetAttribute(gather_kernel,
                         cudaFuncAttributeMaxDynamicSharedMemorySize,
                         CG * HW * (int)sizeof(float));

    zero_cnt_kernel<<<(NG * HW + 255) / 256, 256>>>();

    // 8*4096*4096 floats = 33,554,432 float4s; 256 threads/block -> 131072 blocks
    extract_kernel<<<(NG * HW * (HW / 4)) / 256, 256>>>(mt);

    gather_kernel<<<NG * (CH / CG), 256, CG * HW * (int)sizeof(float)>>>(x, out);
}

// round 4
// speedup vs baseline: 1.1253x; 1.1253x over previous
#include <cuda_runtime.h>
#include <stdint.h>

#define NG 8
#define HW 4096          // 64*64 = 2^12
#define CH 256
#define CG 4             // channels per gather block

#define EBLK 2048
#define ETHR 256
#define EUNROLL 8
// total float4 = NG*HW*HW/4 = 33,554,432 ; per-thread = 64 ; outer iters = 8
#define EITERS ((NG * HW * (HW / 4)) / (EBLK * ETHR * EUNROLL))

// Scratch (device globals — no allocation allowed).
// Per (g, j): count + up to 4 (source index, coefficient) pairs.
__device__ int    g_cnt[NG * HW];
__device__ int4   g_idx4[NG * HW];
__device__ float4 g_val4[NG * HW];

// Pass 1: stream the dense matrix, extract nonzeros into fixed 4-slot CSR.
// mt layout: [g, i, j] row-major; element (g,i,j) at g*2^24 + i*2^12 + j.
__global__ void __launch_bounds__(ETHR) extract_kernel(const float4* __restrict__ mt4) {
    const long long T = (long long)EBLK * ETHR;           // coalesced stride
    const long long t = (long long)blockIdx.x * ETHR + threadIdx.x;

    #pragma unroll 1
    for (int it = 0; it < EITERS; ++it) {
        const long long b0 = (long long)it * EUNROLL * T + t;

        // Front-batched independent streaming loads → MLP = EUNROLL per thread.
        float4 v[EUNROLL];
        #pragma unroll
        for (int k = 0; k < EUNROLL; ++k)
            v[k] = __ldcs(&mt4[b0 + (long long)k * T]);

        #pragma unroll
        for (int k = 0; k < EUNROLL; ++k) {
            // Coefficients are non-negative: zero ⇔ bit pattern 0.
            uint32_t ux = __float_as_uint(v[k].x);
            uint32_t uy = __float_as_uint(v[k].y);
            uint32_t uz = __float_as_uint(v[k].z);
            uint32_t uw = __float_as_uint(v[k].w);
            if ((ux | uy | uz | uw) != 0u) {
                long long e = (b0 + (long long)k * T) << 2;   // element index
                int g   = (int)(e >> 24);                     // HW*HW = 2^24
                int rem = (int)(e & 0xFFFFFF);
                int i   = rem >> 12;
                int j0  = rem & 0xFFF;
                int gb  = g * HW;

                float vv[4] = {v[k].x, v[k].y, v[k].z, v[k].w};
                #pragma unroll
                for (int c = 0; c < 4; ++c) {
                    if (vv[c] != 0.0f) {
                        int j = j0 + c;
                        int p = atomicAdd(&g_cnt[gb + j], 1);
                        if (p < 4) {
                            ((int*)g_idx4)[(long long)(gb + j) * 4 + p]   = i;
                            ((float*)g_val4)[(long long)(gb + j) * 4 + p] = vv[c];
                        }
                    }
                }
            }
        }
    }
}

__device__ __forceinline__ void cswap(int& ia, float& va, int& ib, float& vb) {
    if (ia > ib) {
        int ti = ia; ia = ib; ib = ti;
        float tv = va; va = vb; vb = tv;
    }
}

// Pass 2: gather. Block = (g, 4-channel group). x rows staged in smem.
__global__ void __launch_bounds__(256) gather_kernel(const float* __restrict__ x,
                                                     float* __restrict__ out) {
    extern __shared__ float xs[];                 // CG * HW floats = 64 KB
    int g     = blockIdx.x / (CH / CG);
    int cbase = (blockIdx.x % (CH / CG)) * CG;

    const float* xg = x + ((long long)g * CH + cbase) * HW;   // CG contiguous rows
    const float4* xg4 = (const float4*)xg;
    float4* xs4 = (float4*)xs;
    for (int t = threadIdx.x; t < (CG * HW) / 4; t += blockDim.x)
        xs4[t] = xg4[t];
    __syncthreads();

    int gb = g * HW;
    for (int j = threadIdx.x; j < HW; j += blockDim.x) {
        int    cnt = g_cnt[gb + j];
        int4   id  = g_idx4[gb + j];
        float4 vl  = g_val4[gb + j];

        int   i0 = id.x, i1 = id.y, i2 = id.z, i3 = id.w;
        float v0 = vl.x, v1 = vl.y, v2 = vl.z, v3 = vl.w;
        if (cnt < 4) { i3 = 0; v3 = 0.0f; }
        if (cnt < 3) { i2 = 0; v2 = 0.0f; }
        if (cnt < 2) { i1 = 0; v1 = 0.0f; }
        if (cnt < 1) { i0 = 0; v0 = 0.0f; }

        // Sort 4 pairs by source index (deterministic summation order
        // regardless of atomic append order in pass 1).
        cswap(i0, v0, i1, v1);
        cswap(i2, v2, i3, v3);
        cswap(i0, v0, i2, v2);
        cswap(i1, v1, i3, v3);
        cswap(i1, v1, i2, v2);

        #pragma unroll
        for (int c = 0; c < CG; c++) {
            const float* row = xs + c * HW;
            float s = fmaf(v3, row[i3],
                      fmaf(v2, row[i2],
                      fmaf(v1, row[i1],
                           v0 * row[i0])));
            out[((long long)(g * CH + cbase + c)) * HW + j] = s;
        }
    }
}

extern "C" void kernel_launch(void* const* d_in, const int* in_sizes, int n_in,
                              void* d_out, int out_size) {
    const float* x  = (const float*)d_in[0];   // [8, 256, 64, 64]
    const float* mt = (const float*)d_in[1];   // [8, 4096, 4096]
    float* out = (float*)d_out;

    (void)in_sizes; (void)n_in; (void)out_size;

    cudaFuncSetAttribute(gather_kernel,
                         cudaFuncAttributeMaxDynamicSharedMemorySize,
                         CG * HW * (int)sizeof(float));

    // Zero the counters via a graph memset node (cheaper than a kernel).
    void* cnt_ptr = nullptr;
    cudaGetSymbolAddress(&cnt_ptr, g_cnt);
    cudaMemsetAsync(cnt_ptr, 0, NG * HW * sizeof(int), 0);

    extract_kernel<<<EBLK, ETHR>>>((const float4*)mt);

    gather_kernel<<<NG * (CH / CG), 256, CG * HW * (int)sizeof(float)>>>(x, out);
}